// round 14
// baseline (speedup 1.0000x reference)
#include <cuda_runtime.h>
#include <cuda_bf16.h>
#include <cstdint>
#include <math.h>

#define Bb    8
#define NPIX  256
#define Mm    8192
#define N_CP  24576
#define N_CA  24576
#define ROWS2 16384

// tiling: per type (cos=0, sin=1): 74 CTAs, 68x112 rows + 6x96 rows = 8192
#define CTAS_TYPE 74
#define BIG_N     68
#define R_BIG     112
#define R_SML     96
#define BIG_END   7616        // 68*112
#define TYPE_OFF  4194304     // 8192 rows * 512 B

// ---------------- device scratch (static, allowed) ----------------
__device__ __align__(1024) unsigned char g_Apack[(size_t)2 * TYPE_OFF];   // 8 MB
__device__ __align__(1024) unsigned char g_Bpack[(size_t)Bb * 2 * 2 * 65536];
__device__ float2 g_EuF[(size_t)Mm * 128];
__device__ float2 g_IcF[(size_t)Bb * 128];
__device__ float g_p1[(size_t)ROWS2 * Bb * 4];
__device__ float g_p2[(size_t)ROWS2 * Bb * 4];
__device__ float2 g_visc[(size_t)Bb * Mm];

// ---------------- helpers ----------------
__device__ __forceinline__ uint32_t smem_u32(const void* p) {
    uint32_t a;
    asm("{ .reg .u64 t; cvta.to.shared.u64 t, %1; cvt.u32.u64 %0, t; }" : "=r"(a) : "l"(p));
    return a;
}
__device__ __forceinline__ void cpasync16(uint32_t dst, const void* src) {
    asm volatile("cp.async.cg.shared.global [%0], [%1], 16;" :: "r"(dst), "l"(src));
}
__device__ __forceinline__ unsigned swz(unsigned off) { return off ^ ((off >> 3) & 0x70); }

#define LDSM_X4(r0, r1, r2, r3, a) \
    asm volatile("ldmatrix.sync.aligned.m8n8.x4.shared.b16 {%0,%1,%2,%3}, [%4];" \
                 : "=r"(r0), "=r"(r1), "=r"(r2), "=r"(r3) : "r"(a))

#define MMA_BF16(d, a0, a1, a2, a3, b0, b1) \
    asm volatile("mma.sync.aligned.m16n8k16.row.col.f32.bf16.bf16.f32 " \
                 "{%0,%1,%2,%3},{%4,%5,%6,%7},{%8,%9},{%0,%1,%2,%3};" \
                 : "+f"((d)[0]), "+f"((d)[1]), "+f"((d)[2]), "+f"((d)[3]) \
                 : "r"(a0), "r"(a1), "r"(a2), "r"(a3), "r"(b0), "r"(b1))

__device__ __forceinline__ float reduce_pi(float a) {
    const double TP = 6.283185307179586476925286766559;
    float n = rintf(a * 0.15915494309189535f);
    return (float)((double)a - (double)n * TP);
}
__device__ __forceinline__ float fast_atan2(float y, float x) {
    float ax = fabsf(x), ay = fabsf(y);
    float mx = fmaxf(ax, ay), mn = fminf(ax, ay);
    float t = __fdividef(mn, mx);
    float t2 = t * t;
    float p = -0.01172120f;
    p = fmaf(p, t2,  0.05265332f);
    p = fmaf(p, t2, -0.11643287f);
    p = fmaf(p, t2,  0.19354346f);
    p = fmaf(p, t2, -0.33262347f);
    p = fmaf(p, t2,  0.99997726f);
    float r = p * t;
    if (ay > ax) r = 1.57079632679f - r;
    if (x < 0.f) r = 3.14159265359f - r;
    return (y < 0.f) ? -r : r;
}

__device__ __forceinline__ int lo_x(int P) { return (P < 127) ? (P + 1) : 0; }
__device__ __forceinline__ int hi_x(int P) { return (P < 127) ? (255 - P) : 128; }

__device__ __forceinline__ void bf16_split(float v, unsigned short& h, unsigned short& l) {
    __nv_bfloat16 hb = __float2bfloat16(v);
    h = __bfloat16_as_ushort(hb);
    l = __bfloat16_as_ushort(__float2bfloat16(v - __bfloat162float(hb)));
}
__device__ __forceinline__ uint4 pack8(const unsigned short* a) {
    uint4 u;
    u.x = (uint32_t)a[0] | ((uint32_t)a[1] << 16);
    u.y = (uint32_t)a[2] | ((uint32_t)a[3] << 16);
    u.z = (uint32_t)a[4] | ((uint32_t)a[5] << 16);
    u.w = (uint32_t)a[6] | ((uint32_t)a[7] << 16);
    return u;
}

// ---------------- prep: recurrence trig + variable-tile A pack + B pack ----------------
#define PREP_N (Mm * 8 + 32768 + Bb * 128)

__global__ void prep_kernel(const float* __restrict__ kt, const float* __restrict__ img) {
    int idx = blockIdx.x * blockDim.x + threadIdx.x;
    if (idx < Mm * 8) {
        int m = idx >> 3, oct = idx & 7;
        float kv = kt[m], ku = kt[Mm + m];
        float t0f = (float)(oct * 16 + 1);
        float cv = __cosf(reduce_pi(kv * t0f)), sv = __sinf(reduce_pi(kv * t0f));
        float rv = reduce_pi(kv);
        float cvs = __cosf(rv), svs = __sinf(rv);
        float cu = __cosf(reduce_pi(ku * t0f)), su = __sinf(reduce_pi(ku * t0f));
        float ru = reduce_pi(ku);
        float cus = __cosf(ru), sus = __sinf(ru);
        // variable-height tile coords
        int r, R;
        if (m < BIG_END) { int ti = m / R_BIG; r = m - ti * R_BIG; R = R_BIG; }
        else             { int q = m - BIG_END; int tj = q / R_SML; r = q - tj * R_SML; R = R_SML; }
        int chunk = oct >> 2;
        int blk = 256 * R, loOff = 128 * R;
        size_t baseC = (size_t)512 * (m - r) + (size_t)chunk * blk;          // cos type
        size_t baseS = baseC + TYPE_OFF;                                      // sin type
        float2* euf = g_EuF + (size_t)m * 128;
        #pragma unroll
        for (int g2 = 0; g2 < 2; g2++) {
            unsigned short ch[8], cl[8], sh8[8], sl8[8];
            #pragma unroll
            for (int j = 0; j < 8; j++) {
                bf16_split(cv, ch[j], cl[j]);
                bf16_split(-sv, sh8[j], sl8[j]);
                int dd = oct * 16 + g2 * 8 + j + 1;       // 1..128
                int P = (dd == 128) ? 127 : (127 - dd);
                euf[P] = make_float2(cu, su);
                float ncv = fmaf(cv, cvs, -sv * svs);
                float nsv = fmaf(sv, cvs,  cv * svs);
                cv = ncv;  sv = nsv;
                float ncu = fmaf(cu, cus, -su * sus);
                float nsu = fmaf(su, cus,  cu * sus);
                cu = ncu;  su = nsu;
            }
            unsigned off = swz((unsigned)(r * 128 + ((oct & 3) * 16 + g2 * 8) * 2));
            *(uint4*)(g_Apack + baseC + off)         = pack8(ch);
            *(uint4*)(g_Apack + baseC + loOff + off) = pack8(cl);
            *(uint4*)(g_Apack + baseS + off)         = pack8(sh8);
            *(uint4*)(g_Apack + baseS + loOff + off) = pack8(sl8);
        }
    } else if (idx < Mm * 8 + 32768) {
        int k = idx - Mm * 8;
        int b = k >> 12, rem = k & 4095, tg = rem >> 8, x = rem & 255;
        const float* ib = img + (size_t)b * NPIX * NPIX;
        unsigned short Sh[8], Sl[8], Ah8[8], Al8[8];
        #pragma unroll
        for (int i = 0; i < 8; i++) {
            int t = tg * 8 + i + 1;
            float top = (t < 128) ? ib[(128 + t) * NPIX + x] : 0.f;
            float bot = ib[(128 - t) * NPIX + x];
            bf16_split(top + bot, Sh[i], Sl[i]);
            bf16_split(top - bot, Ah8[i], Al8[i]);
        }
        int chunk = tg >> 3;
        unsigned off = swz((unsigned)(x * 128 + (tg & 7) * 16));
        size_t bS = (size_t)((b * 2 + 0) * 2 + chunk) * 65536;
        size_t bA = (size_t)((b * 2 + 1) * 2 + chunk) * 65536;
        *(uint4*)(g_Bpack + bS + off)         = pack8(Sh);
        *(uint4*)(g_Bpack + bS + 32768 + off) = pack8(Sl);
        *(uint4*)(g_Bpack + bA + off)         = pack8(Ah8);
        *(uint4*)(g_Bpack + bA + 32768 + off) = pack8(Al8);
    } else {
        int k = idx - Mm * 8 - 32768;
        if (k >= Bb * 128) return;
        int b = k >> 7, P = k & 127;
        const float* ir = img + ((size_t)b * NPIX + 128) * NPIX;
        float il = ir[lo_x(P)], ih = ir[hi_x(P)];
        g_IcF[k] = make_float2(il + ih, il - ih);
    }
}

// ---------------- main GEMM: 148 CTAs x 896 threads, m16n64 warp tile ----------------
#define SMEM_TOT (2 * (65536 + 256 * R_BIG))   // 188416

__device__ __forceinline__ void load_chunk(uint32_t sb, int stage, int SS, size_t abase,
                                           int R, int type, int cc, int tid) {
    int b = cc >> 1, c = cc & 1;
    uint32_t dst = sb + stage * SS;
    // B at stage+0 (hi 32K | lo 32K)
    const float4* srcB = (const float4*)(g_Bpack + (size_t)((b * 2 + type) * 2 + c) * 65536);
    for (int i = tid; i < 4096; i += 896) cpasync16(dst + i * 16, srcB + i);
    // A at stage+65536 (hi 128R | lo 128R)
    const float4* srcA = (const float4*)(g_Apack + abase + (size_t)c * (256 * R));
    int nA = 16 * R;
    for (int i = tid; i < nA; i += 896) cpasync16(dst + 65536 + i * 16, srcA + i);
    asm volatile("cp.async.commit_group;" ::: "memory");
}

__global__ __launch_bounds__(896, 1) void vis_mma_kernel() {
    extern __shared__ unsigned char smem[];
    uint32_t sb = smem_u32(smem);
    const int tid  = threadIdx.x;
    const int warp = tid >> 5, lane = tid & 31;
    const int wm   = warp >> 2;         // 0..6, 16 rows each
    const int wn   = warp & 3;          // 0..3, 64 cols each
    const int bid  = blockIdx.x;
    const int type = (bid >= CTAS_TYPE) ? 1 : 0;
    const int ti   = bid - type * CTAS_TYPE;
    const int R    = (ti < BIG_N) ? R_BIG : R_SML;
    const int base_rows = (ti < BIG_N) ? R_BIG * ti : BIG_END + R_SML * (ti - BIG_N);
    const size_t abase  = (size_t)type * TYPE_OFF + (size_t)512 * base_rows;
    const int SS = 65536 + 256 * R;
    const bool isCos = (type == 0);
    const bool act = (wm * 16 < R);

    const uint32_t kA2 = (lane >> 4) * 16;
    const uint32_t kB2 = ((lane >> 3) & 1) * 16;
    const int arow_r = wm * 16 + (lane & 15);
    const uint32_t aRow = arow_r * 128, aXor = (arow_r & 7) << 4;
    uint32_t bRow[4], bXor[4];
    #pragma unroll
    for (int p = 0; p < 4; p++) {
        int q  = p * 16 + ((lane >> 4) & 1) * 8 + (lane & 7);
        int nt = q >> 3, cc8 = q & 7;
        int P  = wn * 32 + nt * 4 + (cc8 >> 1);
        int x  = (cc8 & 1) ? hi_x(P) : lo_x(P);
        bRow[p] = x * 128;  bXor[p] = (x & 7) << 4;
    }

    float acc[32];
    #pragma unroll
    for (int i = 0; i < 32; i++) acc[i] = 0.f;

    load_chunk(sb, 0, SS, abase, R, type, 0, tid);
    load_chunk(sb, 1, SS, abase, R, type, 1, tid);

    for (int cc = 0; cc < 16; cc++) {
        const int s = cc & 1, b = cc >> 1, c = cc & 1;
        if (cc + 2 < 16) asm volatile("cp.async.wait_group 1;" ::: "memory");
        else             asm volatile("cp.async.wait_group 0;" ::: "memory");
        __syncthreads();

        const uint32_t st = sb + s * SS;
        if (act) {
            const uint32_t aBaseH = st + 65536;
            const uint32_t aBaseL = st + 65536 + 128 * R;
            #pragma unroll
            for (int ks = 0; ks < 4; ks++) {
                uint32_t ah[4], al[4];
                uint32_t k2a = ks * 32 + kA2;
                LDSM_X4(ah[0], ah[1], ah[2], ah[3], aBaseH + aRow + (k2a ^ aXor));
                LDSM_X4(al[0], al[1], al[2], al[3], aBaseL + aRow + (k2a ^ aXor));
                #pragma unroll
                for (int p = 0; p < 4; p++) {
                    uint32_t k2 = ks * 32 + kB2;
                    uint32_t offBH = st +         bRow[p] + (k2 ^ bXor[p]);
                    uint32_t offBL = st + 32768 + bRow[p] + (k2 ^ bXor[p]);
                    uint32_t h0, h1, h2, h3, l0, l1, l2, l3;
                    LDSM_X4(h0, h1, h2, h3, offBH);
                    MMA_BF16(&acc[(2 * p) * 4],     ah[0], ah[1], ah[2], ah[3], h0, h1);
                    MMA_BF16(&acc[(2 * p + 1) * 4], ah[0], ah[1], ah[2], ah[3], h2, h3);
                    MMA_BF16(&acc[(2 * p) * 4],     al[0], al[1], al[2], al[3], h0, h1);
                    MMA_BF16(&acc[(2 * p + 1) * 4], al[0], al[1], al[2], al[3], h2, h3);
                    LDSM_X4(l0, l1, l2, l3, offBL);
                    MMA_BF16(&acc[(2 * p) * 4],     ah[0], ah[1], ah[2], ah[3], l0, l1);
                    MMA_BF16(&acc[(2 * p + 1) * 4], ah[0], ah[1], ah[2], ah[3], l2, l3);
                }
            }
        }
        __syncthreads();
        if (cc + 2 < 16) load_chunk(sb, s, SS, abase, R, type, cc + 2, tid);

        if (c == 1 && act) {
            const int g = lane >> 2, t4 = lane & 3;
            const bool special = (wn == 3) && (t4 == 3);
            int rowt = base_rows + wm * 16 + g;
            int mA = rowt, mB = rowt + 8;
            const float2* tcA = g_EuF + (size_t)mA * 128;
            const float2* tcB = g_EuF + (size_t)mB * 128;
            float p1a = 0.f, p2a = 0.f, p1b = 0.f, p2b = 0.f;
            #pragma unroll
            for (int nt = 0; nt < 8; nt++) {
                int P = wn * 32 + nt * 4 + t4;
                float2 csA = tcA[P];
                float2 csB = tcB[P];
                float* d = &acc[nt * 4];
                float s0 = d[0] + d[1], a0 = d[0] - d[1];
                float s1 = d[2] + d[3], a1 = d[2] - d[3];
                float tHa = d[1], tHb = d[3];
                if (isCos) {
                    float2 ic = g_IcF[b * 128 + P];
                    s0 += ic.x;  a0 += ic.y;  s1 += ic.x;  a1 += ic.y;
                    float ih = 0.5f * (ic.x - ic.y);
                    tHa += ih;  tHb += ih;
                }
                p1a = fmaf(s0, csA.x, p1a);  p2a = fmaf(a0, csA.y, p2a);
                p1b = fmaf(s1, csB.x, p1b);  p2b = fmaf(a1, csB.y, p2b);
                if (special && nt == 7) {
                    p1a = fmaf(tHa, 1.f - csA.x, p1a);  p2a = fmaf(tHa, csA.y, p2a);
                    p1b = fmaf(tHb, 1.f - csB.x, p1b);  p2b = fmaf(tHb, csB.y, p2b);
                }
                d[0] = d[1] = d[2] = d[3] = 0.f;
            }
            #pragma unroll
            for (int sh = 1; sh <= 2; sh <<= 1) {
                p1a += __shfl_xor_sync(0xffffffffu, p1a, sh);
                p2a += __shfl_xor_sync(0xffffffffu, p2a, sh);
                p1b += __shfl_xor_sync(0xffffffffu, p1b, sh);
                p2b += __shfl_xor_sync(0xffffffffu, p2b, sh);
            }
            if (t4 == 0) {
                size_t rg = (size_t)type * Mm + rowt;
                size_t i1 = (rg * Bb + b) * 4 + wn;
                size_t i2 = ((rg + 8) * Bb + b) * 4 + wn;
                g_p1[i1] = p1a;  g_p2[i1] = p2a;
                g_p1[i2] = p1b;  g_p2[i2] = p2b;
            }
        }
    }
}

// ---------------- combine ----------------
__global__ void combine_kernel(const float* __restrict__ pf, float* __restrict__ out) {
    int idx = blockIdx.x * blockDim.x + threadIdx.x;
    if (idx >= Bb * Mm) return;
    int b = idx >> 13, m = idx & (Mm - 1);
    size_t i1 = ((size_t)m * Bb + b) * 4;
    size_t i2 = ((size_t)(m + Mm) * Bb + b) * 4;
    float4 q1 = *(const float4*)(g_p1 + i1);
    float4 q2 = *(const float4*)(g_p2 + i1);
    float4 q3 = *(const float4*)(g_p1 + i2);
    float4 q4 = *(const float4*)(g_p2 + i2);
    float trr = q1.x + q1.y + q1.z + q1.w;
    float tri = q2.x + q2.y + q2.z + q2.w;
    float tir = q3.x + q3.y + q3.z + q3.w;
    float tii = q4.x + q4.y + q4.z + q4.w;
    float kr = trr - tii, ki = tri + tir;
    float pr = pf[m], pi = pf[Mm + m];
    float vr = kr * pr - ki * pi;
    float vi = kr * pi + ki * pr;
    out[(size_t)b * 2 * Mm + m]      = vr;
    out[(size_t)b * 2 * Mm + Mm + m] = vi;
    out[(size_t)Bb * 2 * Mm + (size_t)b * Mm + m] = sqrtf(vr * vr + vi * vi + 1e-16f);
    g_visc[(size_t)b * Mm + m] = make_float2(vr, vi);
}

// ---------------- fused cphase + logcamp ----------------
__global__ void obs_kernel(const float* __restrict__ sign, const int* __restrict__ cind,
                           const int* __restrict__ aind,
                           float* __restrict__ out_cp, float* __restrict__ out_lc) {
    int idx = blockIdx.x * blockDim.x + threadIdx.x;
    if (idx < Bb * N_CP) {
        int b = idx / N_CP, n = idx - b * N_CP;
        const float2* vb = g_visc + (size_t)b * Mm;
        float s = 0.f;
        #pragma unroll
        for (int k = 0; k < 3; k++) {
            float2 v = vb[cind[k * N_CP + n]];
            s = fmaf(sign[k * N_CP + n], fast_atan2(v.y, v.x), s);
        }
        out_cp[idx] = s * 57.29577951308232f;
    } else {
        int j = idx - Bb * N_CP;
        if (j >= Bb * N_CA) return;
        int b = j / N_CA, n = j - b * N_CA;
        const float2* vb = g_visc + (size_t)b * Mm;
        float s[4];
        #pragma unroll
        for (int k = 0; k < 4; k++) {
            float2 v = vb[aind[k * N_CA + n]];
            s[k] = fmaf(v.x, v.x, fmaf(v.y, v.y, 1e-16f));
        }
        out_lc[j] = 0.5f * (__logf(s[0]) + __logf(s[1]) - __logf(s[2]) - __logf(s[3]));
    }
}

extern "C" void kernel_launch(void* const* d_in, const int* in_sizes, int n_in,
                              void* d_out, int out_size) {
    const float* images      = (const float*)d_in[0];
    const float* ktraj       = (const float*)d_in[1];
    const float* pulsefac    = (const float*)d_in[2];
    const float* cphase_sign = (const float*)d_in[3];
    const int*   cphase_ind  = (const int*)d_in[4];
    const int*   camp_ind    = (const int*)d_in[5];
    float* out = (float*)d_out;

    float* out_cp = out + (size_t)Bb * 2 * Mm + (size_t)Bb * Mm;
    float* out_lc = out_cp + (size_t)Bb * N_CP;

    cudaFuncSetAttribute(vis_mma_kernel, cudaFuncAttributeMaxDynamicSharedMemorySize, SMEM_TOT);

    prep_kernel<<<(PREP_N + 255) / 256, 256>>>(ktraj, images);
    vis_mma_kernel<<<2 * CTAS_TYPE, 896, SMEM_TOT>>>();
    combine_kernel<<<(Bb * Mm + 255) / 256, 256>>>(pulsefac, out);
    obs_kernel<<<(Bb * (N_CP + N_CA) + 255) / 256, 256>>>(cphase_sign, cphase_ind, camp_ind,
                                                          out_cp, out_lc);
}

// round 15
// speedup vs baseline: 1.1261x; 1.1261x over previous
#include <cuda_runtime.h>
#include <cuda_bf16.h>
#include <cstdint>
#include <math.h>

#define Bb    8
#define NPIX  256
#define Mm    8192
#define N_CP  24576
#define N_CA  24576
#define ROWS2 16384          // 2*Mm (cos rows then sin rows)
#define TILES 128            // ROWS2 / 128

// ---------------- device scratch (static, allowed) ----------------
__device__ __align__(1024) unsigned char g_Apack[(size_t)TILES * 2 * 32768];
__device__ __align__(1024) unsigned char g_Bpack[(size_t)Bb * 2 * 2 * 65536];
__device__ float2 g_EuF[(size_t)Mm * 128];     // folded Eu table (C,S) per pair
__device__ float2 g_IcF[(size_t)Bb * 128];     // folded img center row per pair
__device__ float g_p1[(size_t)ROWS2 * Bb];     // reduced partials (1 per row per b)
__device__ float g_p2[(size_t)ROWS2 * Bb];
__device__ float2 g_visc[(size_t)Bb * Mm];     // packed (re,im) for gathers

// ---------------- helpers ----------------
__device__ __forceinline__ uint32_t smem_u32(const void* p) {
    uint32_t a;
    asm("{ .reg .u64 t; cvta.to.shared.u64 t, %1; cvt.u32.u64 %0, t; }" : "=r"(a) : "l"(p));
    return a;
}
__device__ __forceinline__ void cpasync16(uint32_t dst, const void* src) {
    asm volatile("cp.async.cg.shared.global [%0], [%1], 16;" :: "r"(dst), "l"(src));
}
__device__ __forceinline__ unsigned swz(unsigned off) { return off ^ ((off >> 3) & 0x70); }

#define LDSM_X4(r0, r1, r2, r3, a) \
    asm volatile("ldmatrix.sync.aligned.m8n8.x4.shared.b16 {%0,%1,%2,%3}, [%4];" \
                 : "=r"(r0), "=r"(r1), "=r"(r2), "=r"(r3) : "r"(a))

#define MMA_BF16(d, a0, a1, a2, a3, b0, b1) \
    asm volatile("mma.sync.aligned.m16n8k16.row.col.f32.bf16.bf16.f32 " \
                 "{%0,%1,%2,%3},{%4,%5,%6,%7},{%8,%9},{%0,%1,%2,%3};" \
                 : "+f"((d)[0]), "+f"((d)[1]), "+f"((d)[2]), "+f"((d)[3]) \
                 : "r"(a0), "r"(a1), "r"(a2), "r"(a3), "r"(b0), "r"(b1))

__device__ __forceinline__ float reduce_pi(float a) {
    const double TP = 6.283185307179586476925286766559;
    float n = rintf(a * 0.15915494309189535f);
    return (float)((double)a - (double)n * TP);
}
__device__ __forceinline__ float fast_atan2(float y, float x) {
    float ax = fabsf(x), ay = fabsf(y);
    float mx = fmaxf(ax, ay), mn = fminf(ax, ay);
    float t = __fdividef(mn, mx);
    float t2 = t * t;
    float p = -0.01172120f;
    p = fmaf(p, t2,  0.05265332f);
    p = fmaf(p, t2, -0.11643287f);
    p = fmaf(p, t2,  0.19354346f);
    p = fmaf(p, t2, -0.33262347f);
    p = fmaf(p, t2,  0.99997726f);
    float r = p * t;
    if (ay > ax) r = 1.57079632679f - r;
    if (x < 0.f) r = 3.14159265359f - r;
    return (y < 0.f) ? -r : r;
}

// pair P -> x columns: lo = P+1 (P<127) else 0 ; hi = 255-P (P<127) else 128
__device__ __forceinline__ int lo_x(int P) { return (P < 127) ? (P + 1) : 0; }
__device__ __forceinline__ int hi_x(int P) { return (P < 127) ? (255 - P) : 128; }

__device__ __forceinline__ void bf16_split(float v, unsigned short& h, unsigned short& l) {
    __nv_bfloat16 hb = __float2bfloat16(v);
    h = __bfloat16_as_ushort(hb);
    l = __bfloat16_as_ushort(__float2bfloat16(v - __bfloat162float(hb)));
}
__device__ __forceinline__ uint4 pack8(const unsigned short* a) {
    uint4 u;
    u.x = (uint32_t)a[0] | ((uint32_t)a[1] << 16);
    u.y = (uint32_t)a[2] | ((uint32_t)a[3] << 16);
    u.z = (uint32_t)a[4] | ((uint32_t)a[5] << 16);
    u.w = (uint32_t)a[6] | ((uint32_t)a[7] << 16);
    return u;
}

// ---------------- prep: rotation-recurrence trig + vectorized packing ----------------
#define PREP_N (Mm * 8 + 32768 + Bb * 128)

__global__ void prep_kernel(const float* __restrict__ kt, const float* __restrict__ img) {
    int idx = blockIdx.x * blockDim.x + threadIdx.x;
    if (idx < Mm * 8) {
        int m = idx >> 3, oct = idx & 7;
        float kv = kt[m], ku = kt[Mm + m];
        float t0f = (float)(oct * 16 + 1);
        float cv = __cosf(reduce_pi(kv * t0f)), sv = __sinf(reduce_pi(kv * t0f));
        float rv = reduce_pi(kv);
        float cvs = __cosf(rv), svs = __sinf(rv);
        float cu = __cosf(reduce_pi(ku * t0f)), su = __sinf(reduce_pi(ku * t0f));
        float ru = reduce_pi(ku);
        float cus = __cosf(ru), sus = __sinf(ru);
        int r = m & 127;
        int chunk = oct >> 2;
        size_t baseC = (size_t)((m >> 7) * 2 + chunk) * 32768;
        size_t baseS = (size_t)((64 + (m >> 7)) * 2 + chunk) * 32768;
        float2* euf = g_EuF + (size_t)m * 128;
        #pragma unroll
        for (int g2 = 0; g2 < 2; g2++) {
            unsigned short ch[8], cl[8], sh8[8], sl8[8];
            #pragma unroll
            for (int j = 0; j < 8; j++) {
                bf16_split(cv, ch[j], cl[j]);
                bf16_split(-sv, sh8[j], sl8[j]);
                int dd = oct * 16 + g2 * 8 + j + 1;       // 1..128
                int P = (dd == 128) ? 127 : (127 - dd);
                euf[P] = make_float2(cu, su);
                float ncv = fmaf(cv, cvs, -sv * svs);
                float nsv = fmaf(sv, cvs,  cv * svs);
                cv = ncv;  sv = nsv;
                float ncu = fmaf(cu, cus, -su * sus);
                float nsu = fmaf(su, cus,  cu * sus);
                cu = ncu;  su = nsu;
            }
            unsigned off = swz((unsigned)(r * 128 + ((oct & 3) * 16 + g2 * 8) * 2));
            *(uint4*)(g_Apack + baseC + off)         = pack8(ch);
            *(uint4*)(g_Apack + baseC + 16384 + off) = pack8(cl);
            *(uint4*)(g_Apack + baseS + off)         = pack8(sh8);
            *(uint4*)(g_Apack + baseS + 16384 + off) = pack8(sl8);
        }
    } else if (idx < Mm * 8 + 32768) {
        int k = idx - Mm * 8;
        int b = k >> 12, rem = k & 4095, tg = rem >> 8, x = rem & 255;
        const float* ib = img + (size_t)b * NPIX * NPIX;
        unsigned short Sh[8], Sl[8], Ah8[8], Al8[8];
        #pragma unroll
        for (int i = 0; i < 8; i++) {
            int t = tg * 8 + i + 1;
            float top = (t < 128) ? ib[(128 + t) * NPIX + x] : 0.f;
            float bot = ib[(128 - t) * NPIX + x];
            bf16_split(top + bot, Sh[i], Sl[i]);
            bf16_split(top - bot, Ah8[i], Al8[i]);
        }
        int chunk = tg >> 3;
        unsigned off = swz((unsigned)(x * 128 + (tg & 7) * 16));
        size_t bS = (size_t)((b * 2 + 0) * 2 + chunk) * 65536;
        size_t bA = (size_t)((b * 2 + 1) * 2 + chunk) * 65536;
        *(uint4*)(g_Bpack + bS + off)         = pack8(Sh);
        *(uint4*)(g_Bpack + bS + 32768 + off) = pack8(Sl);
        *(uint4*)(g_Bpack + bA + off)         = pack8(Ah8);
        *(uint4*)(g_Bpack + bA + 32768 + off) = pack8(Al8);
    } else {
        int k = idx - Mm * 8 - 32768;
        if (k >= Bb * 128) return;
        int b = k >> 7, P = k & 127;
        const float* ir = img + ((size_t)b * NPIX + 128) * NPIX;
        float il = ir[lo_x(P)], ih = ir[hi_x(P)];
        g_IcF[k] = make_float2(il + ih, il - ih);
    }
}

// ---------------- main GEMM (mma.sync HMMA) + folded Eu epilogue + smem reduce ----------------
#define SMEM_STAGE 98304
#define RED_OFF    196608            // 4KB reduction buffer: [wn][128 rows] float2
#define SMEM_TOT   (196608 + 4096)

__device__ __forceinline__ void load_chunk(uint32_t sb, int stage, int tile, int cc, int tid) {
    int b = cc >> 1, c = cc & 1;
    int type = (tile >= 64) ? 1 : 0;
    uint32_t dst = sb + stage * SMEM_STAGE;
    const float4* srcA = (const float4*)(g_Apack + (size_t)(tile * 2 + c) * 32768);
    #pragma unroll
    for (int i = 0; i < 4; i++) cpasync16(dst + (tid + i * 512) * 16, srcA + tid + i * 512);
    uint32_t dstB = dst + 32768;
    const float4* srcB = (const float4*)(g_Bpack + (size_t)((b * 2 + type) * 2 + c) * 65536);
    #pragma unroll
    for (int i = 0; i < 8; i++) cpasync16(dstB + (tid + i * 512) * 16, srcB + tid + i * 512);
    asm volatile("cp.async.commit_group;" ::: "memory");
}

__device__ __forceinline__ void reduce_rows(uint32_t sb, int tile, int bprev, int tid) {
    if (tid < 128) {
        const float2* buf = (const float2*)(sb == 0 ? 0 : 0);  // placeholder (unused)
    }
}

__global__ __launch_bounds__(512, 1) void vis_mma_kernel() {
    extern __shared__ unsigned char smem[];
    uint32_t sb = smem_u32(smem);
    float2* red = (float2*)(smem + RED_OFF);   // [wn*128 + row]
    const int tid  = threadIdx.x;
    const int warp = tid >> 5, lane = tid & 31;
    const int wm   = warp & 3;
    const int wn   = warp >> 2;
    const int tile = blockIdx.x;
    const bool isCos = tile < 64;

    const uint32_t kA2 = (lane >> 4) * 16;
    const uint32_t kB2 = ((lane >> 3) & 1) * 16;
    uint32_t aRow[2], aXor[2], bRow[4], bXor[4];
    #pragma unroll
    for (int mt = 0; mt < 2; mt++) {
        int r = wm * 32 + mt * 16 + (lane & 15);
        aRow[mt] = r * 128;  aXor[mt] = (r & 7) << 4;
    }
    #pragma unroll
    for (int p = 0; p < 4; p++) {
        int q  = p * 16 + ((lane >> 4) & 1) * 8 + (lane & 7);
        int nt = q >> 3, cc8 = q & 7;
        int P  = wn * 32 + nt * 4 + (cc8 >> 1);
        int x  = (cc8 & 1) ? hi_x(P) : lo_x(P);
        bRow[p] = x * 128;  bXor[p] = (x & 7) << 4;
    }

    float acc[64];
    #pragma unroll
    for (int i = 0; i < 64; i++) acc[i] = 0.f;

    load_chunk(sb, 0, tile, 0, tid);
    load_chunk(sb, 1, tile, 1, tid);

    for (int cc = 0; cc < 16; cc++) {
        const int s = cc & 1, b = cc >> 1, c = cc & 1;
        if (cc + 2 < 16) asm volatile("cp.async.wait_group 1;" ::: "memory");
        else             asm volatile("cp.async.wait_group 0;" ::: "memory");
        __syncthreads();

        // reduce previous b's partials (buffer written at cc-1, safe after barrier)
        if (c == 0 && cc > 0 && tid < 128) {
            int bprev = b - 1;
            float2 a0 = red[tid], a1 = red[128 + tid], a2 = red[256 + tid], a3 = red[384 + tid];
            size_t rg = (size_t)tile * 128 + tid;
            g_p1[rg * Bb + bprev] = a0.x + a1.x + a2.x + a3.x;
            g_p2[rg * Bb + bprev] = a0.y + a1.y + a2.y + a3.y;
        }

        const uint32_t st = sb + s * SMEM_STAGE;
        #pragma unroll
        for (int ks = 0; ks < 4; ks++) {
            uint32_t ah[2][4], al[2][4];
            #pragma unroll
            for (int mt = 0; mt < 2; mt++) {
                uint32_t k2 = ks * 32 + kA2;
                uint32_t offH = st +         aRow[mt] + (k2 ^ aXor[mt]);
                uint32_t offL = st + 16384 + aRow[mt] + (k2 ^ aXor[mt]);
                LDSM_X4(ah[mt][0], ah[mt][1], ah[mt][2], ah[mt][3], offH);
                LDSM_X4(al[mt][0], al[mt][1], al[mt][2], al[mt][3], offL);
            }
            #pragma unroll
            for (int p = 0; p < 4; p++) {
                uint32_t k2 = ks * 32 + kB2;
                uint32_t offBH = st + 32768 + bRow[p] + (k2 ^ bXor[p]);
                uint32_t offBL = st + 65536 + bRow[p] + (k2 ^ bXor[p]);
                uint32_t h0, h1, h2, h3, l0, l1, l2, l3;
                LDSM_X4(h0, h1, h2, h3, offBH);
                #pragma unroll
                for (int mt = 0; mt < 2; mt++) {
                    MMA_BF16(&acc[(mt * 8 + 2 * p) * 4],     ah[mt][0], ah[mt][1], ah[mt][2], ah[mt][3], h0, h1);
                    MMA_BF16(&acc[(mt * 8 + 2 * p + 1) * 4], ah[mt][0], ah[mt][1], ah[mt][2], ah[mt][3], h2, h3);
                    MMA_BF16(&acc[(mt * 8 + 2 * p) * 4],     al[mt][0], al[mt][1], al[mt][2], al[mt][3], h0, h1);
                    MMA_BF16(&acc[(mt * 8 + 2 * p + 1) * 4], al[mt][0], al[mt][1], al[mt][2], al[mt][3], h2, h3);
                }
                LDSM_X4(l0, l1, l2, l3, offBL);
                #pragma unroll
                for (int mt = 0; mt < 2; mt++) {
                    MMA_BF16(&acc[(mt * 8 + 2 * p) * 4],     ah[mt][0], ah[mt][1], ah[mt][2], ah[mt][3], l0, l1);
                    MMA_BF16(&acc[(mt * 8 + 2 * p + 1) * 4], ah[mt][0], ah[mt][1], ah[mt][2], ah[mt][3], l2, l3);
                }
            }
        }
        __syncthreads();                     // all warps done reading stage s
        if (cc + 2 < 16) load_chunk(sb, s, tile, cc + 2, tid);

        if (c == 1) {
            const int g = lane >> 2, t4 = lane & 3;
            const bool special = (wn == 3) && (t4 == 3);
            #pragma unroll
            for (int mt = 0; mt < 2; mt++) {
                int lr = wm * 32 + mt * 16 + g;
                int r0 = tile * 128 + lr;
                int mA = r0 & (Mm - 1);
                int mB = (r0 + 8) & (Mm - 1);
                const float2* tcA = g_EuF + (size_t)mA * 128;
                const float2* tcB = g_EuF + (size_t)mB * 128;
                float p1a = 0.f, p2a = 0.f, p1b = 0.f, p2b = 0.f;
                #pragma unroll
                for (int nt = 0; nt < 8; nt++) {
                    int P = wn * 32 + nt * 4 + t4;
                    float2 csA = tcA[P];
                    float2 csB = tcB[P];
                    float* d = &acc[(mt * 8 + nt) * 4];
                    float s0 = d[0] + d[1], a0 = d[0] - d[1];
                    float s1 = d[2] + d[3], a1 = d[2] - d[3];
                    float tHa = d[1], tHb = d[3];
                    if (isCos) {
                        float2 ic = g_IcF[b * 128 + P];
                        s0 += ic.x;  a0 += ic.y;  s1 += ic.x;  a1 += ic.y;
                        float ih = 0.5f * (ic.x - ic.y);
                        tHa += ih;  tHb += ih;
                    }
                    p1a = fmaf(s0, csA.x, p1a);  p2a = fmaf(a0, csA.y, p2a);
                    p1b = fmaf(s1, csB.x, p1b);  p2b = fmaf(a1, csB.y, p2b);
                    if (special && nt == 7) {
                        p1a = fmaf(tHa, 1.f - csA.x, p1a);  p2a = fmaf(tHa, csA.y, p2a);
                        p1b = fmaf(tHb, 1.f - csB.x, p1b);  p2b = fmaf(tHb, csB.y, p2b);
                    }
                    d[0] = d[1] = d[2] = d[3] = 0.f;
                }
                #pragma unroll
                for (int sh = 1; sh <= 2; sh <<= 1) {
                    p1a += __shfl_xor_sync(0xffffffffu, p1a, sh);
                    p2a += __shfl_xor_sync(0xffffffffu, p2a, sh);
                    p1b += __shfl_xor_sync(0xffffffffu, p1b, sh);
                    p2b += __shfl_xor_sync(0xffffffffu, p2b, sh);
                }
                if (t4 == 0) {
                    red[wn * 128 + lr]     = make_float2(p1a, p2a);
                    red[wn * 128 + lr + 8] = make_float2(p1b, p2b);
                }
            }
        }
    }
    // final reduction for b = 7
    __syncthreads();
    if (tid < 128) {
        float2 a0 = red[tid], a1 = red[128 + tid], a2 = red[256 + tid], a3 = red[384 + tid];
        size_t rg = (size_t)tile * 128 + tid;
        g_p1[rg * Bb + 7] = a0.x + a1.x + a2.x + a3.x;
        g_p2[rg * Bb + 7] = a0.y + a1.y + a2.y + a3.y;
    }
}

// ---------------- combine: partials -> kdata -> vis, visamp, visc ----------------
__global__ void combine_kernel(const float* __restrict__ pf, float* __restrict__ out) {
    int idx = blockIdx.x * blockDim.x + threadIdx.x;
    if (idx >= Bb * Mm) return;
    int b = idx >> 13, m = idx & (Mm - 1);
    float trr = g_p1[(size_t)m * Bb + b];
    float tri = g_p2[(size_t)m * Bb + b];
    float tir = g_p1[(size_t)(m + Mm) * Bb + b];
    float tii = g_p2[(size_t)(m + Mm) * Bb + b];
    float kr = trr - tii, ki = tri + tir;
    float pr = pf[m], pi = pf[Mm + m];
    float vr = kr * pr - ki * pi;
    float vi = kr * pi + ki * pr;
    out[(size_t)b * 2 * Mm + m]      = vr;
    out[(size_t)b * 2 * Mm + Mm + m] = vi;
    out[(size_t)Bb * 2 * Mm + (size_t)b * Mm + m] = sqrtf(vr * vr + vi * vi + 1e-16f);
    g_visc[(size_t)b * Mm + m] = make_float2(vr, vi);
}

// ---------------- fused cphase + logcamp, 2 outputs/thread for MLP ----------------
#define HCP (N_CP / 2)
#define HCA (N_CA / 2)

__global__ void obs_kernel(const float* __restrict__ sign, const int* __restrict__ cind,
                           const int* __restrict__ aind,
                           float* __restrict__ out_cp, float* __restrict__ out_lc) {
    int idx = blockIdx.x * blockDim.x + threadIdx.x;
    if (idx < Bb * HCP) {
        int b = idx / HCP, n = idx - b * HCP;
        const float2* vb = g_visc + (size_t)b * Mm;
        int m0[3], m1[3];
        float sg0[3], sg1[3];
        #pragma unroll
        for (int k = 0; k < 3; k++) {
            m0[k] = cind[k * N_CP + n];
            m1[k] = cind[k * N_CP + n + HCP];
            sg0[k] = sign[k * N_CP + n];
            sg1[k] = sign[k * N_CP + n + HCP];
        }
        float2 v0[3], v1[3];
        #pragma unroll
        for (int k = 0; k < 3; k++) { v0[k] = vb[m0[k]]; v1[k] = vb[m1[k]]; }
        float s0 = 0.f, s1 = 0.f;
        #pragma unroll
        for (int k = 0; k < 3; k++) {
            s0 = fmaf(sg0[k], fast_atan2(v0[k].y, v0[k].x), s0);
            s1 = fmaf(sg1[k], fast_atan2(v1[k].y, v1[k].x), s1);
        }
        out_cp[(size_t)b * N_CP + n]       = s0 * 57.29577951308232f;
        out_cp[(size_t)b * N_CP + n + HCP] = s1 * 57.29577951308232f;
    } else {
        int j = idx - Bb * HCP;
        if (j >= Bb * HCA) return;
        int b = j / HCA, n = j - b * HCA;
        const float2* vb = g_visc + (size_t)b * Mm;
        int m0[4], m1[4];
        #pragma unroll
        for (int k = 0; k < 4; k++) {
            m0[k] = aind[k * N_CA + n];
            m1[k] = aind[k * N_CA + n + HCA];
        }
        float2 v0[4], v1[4];
        #pragma unroll
        for (int k = 0; k < 4; k++) { v0[k] = vb[m0[k]]; v1[k] = vb[m1[k]]; }
        float s0[4], s1[4];
        #pragma unroll
        for (int k = 0; k < 4; k++) {
            s0[k] = fmaf(v0[k].x, v0[k].x, fmaf(v0[k].y, v0[k].y, 1e-16f));
            s1[k] = fmaf(v1[k].x, v1[k].x, fmaf(v1[k].y, v1[k].y, 1e-16f));
        }
        out_lc[(size_t)b * N_CA + n] =
            0.5f * (__logf(s0[0]) + __logf(s0[1]) - __logf(s0[2]) - __logf(s0[3]));
        out_lc[(size_t)b * N_CA + n + HCA] =
            0.5f * (__logf(s1[0]) + __logf(s1[1]) - __logf(s1[2]) - __logf(s1[3]));
    }
}

extern "C" void kernel_launch(void* const* d_in, const int* in_sizes, int n_in,
                              void* d_out, int out_size) {
    const float* images      = (const float*)d_in[0];
    const float* ktraj       = (const float*)d_in[1];
    const float* pulsefac    = (const float*)d_in[2];
    const float* cphase_sign = (const float*)d_in[3];
    const int*   cphase_ind  = (const int*)d_in[4];
    const int*   camp_ind    = (const int*)d_in[5];
    float* out = (float*)d_out;

    float* out_cp = out + (size_t)Bb * 2 * Mm + (size_t)Bb * Mm;
    float* out_lc = out_cp + (size_t)Bb * N_CP;

    cudaFuncSetAttribute(vis_mma_kernel, cudaFuncAttributeMaxDynamicSharedMemorySize, SMEM_TOT);

    prep_kernel<<<(PREP_N + 255) / 256, 256>>>(ktraj, images);
    vis_mma_kernel<<<TILES, 512, SMEM_TOT>>>();
    combine_kernel<<<(Bb * Mm + 255) / 256, 256>>>(pulsefac, out);
    int obs_n = Bb * (HCP + HCA);
    obs_kernel<<<(obs_n + 255) / 256, 256>>>(cphase_sign, cphase_ind, camp_ind,
                                             out_cp, out_lc);
}